// round 5
// baseline (speedup 1.0000x reference)
#include <cuda_runtime.h>
#include <cuda_bf16.h>
#include <math.h>

// ---------------------------------------------------------------------------
// GCNEncoder: enc1 = relu(PN(A @ (x@w1)));
//             pool1 = softmax(PN(A @ (enc1@wp)));  enc2 = relu(PN(A @ (enc1@w2)))
// Bias terms cancel under PairNorm centering and are dropped.
// Layers 2 and 3 are fused into one 128-wide GEMM + one 128-wide SpMM.
// ---------------------------------------------------------------------------

#define N_NODES_MAX 100000
#define D_EMB 128

__device__ float g_buf1[(size_t)N_NODES_MAX * 128]; // support1, then enc1
__device__ float g_buf2[(size_t)N_NODES_MAX * 128]; // agg1, then supportB (fused)
__device__ float g_buf3[(size_t)N_NODES_MAX * 128]; // aggB (fused)
__device__ float g_wcat[128 * 128];                 // [wp | w2]
__device__ float g_csum[256];                       // col sums: [0:128) stage1, [128:256) stage2

// ---------------------------------------------------------------------------
// Zero helpers
// ---------------------------------------------------------------------------
__global__ void zero_f4(float4* p, int n4) {
    int i = blockIdx.x * blockDim.x + threadIdx.x;
    if (i < n4) p[i] = make_float4(0.f, 0.f, 0.f, 0.f);
}

__global__ void zero_small(float* p, int n) {
    int i = blockIdx.x * blockDim.x + threadIdx.x;
    if (i < n) p[i] = 0.f;
}

// ---------------------------------------------------------------------------
// Pack wcat = [wp | w2]   (wp, w2: [128, 64] row-major)
// ---------------------------------------------------------------------------
__global__ void pack_w(const float* __restrict__ wp, const float* __restrict__ w2,
                       float* __restrict__ wcat) {
    int i = blockIdx.x * blockDim.x + threadIdx.x;   // 128*64 = 8192
    if (i >= 128 * 64) return;
    int r = i >> 6, c = i & 63;
    wcat[r * 128 + c]      = wp[i];
    wcat[r * 128 + 64 + c] = w2[i];
}

// ---------------------------------------------------------------------------
// SGEMM: C[M,128] = A[M,K] @ B[K,128].  BM=128, BN=128, BK=16, 256 threads,
// 8x8 register tiles. K must be a multiple of 16 (256 or 128 here).
// ---------------------------------------------------------------------------
__global__ __launch_bounds__(256, 2)
void sgemm_n128(const float* __restrict__ A, const float* __restrict__ B,
                float* __restrict__ C, int M, int K) {
    __shared__ float As[16][128];
    __shared__ float Bs[16][128];

    const int tid = threadIdx.x;
    const int row0 = blockIdx.x * 128;
    const int tx = tid & 15;       // 0..15 -> output cols tx*8..tx*8+7
    const int ty = tid >> 4;       // 0..15 -> output rows ty*8..ty*8+7

    float acc[8][8];
#pragma unroll
    for (int i = 0; i < 8; i++)
#pragma unroll
        for (int j = 0; j < 8; j++) acc[i][j] = 0.f;

    for (int k0 = 0; k0 < K; k0 += 16) {
#pragma unroll
        for (int it = 0; it < 2; it++) {
            int f = tid + it * 256;            // 0..511 (float4 index)
            // A tile: 128 rows x 16 cols = 512 float4
            int ar = f >> 2, ac4 = f & 3;
            float4 av = make_float4(0.f, 0.f, 0.f, 0.f);
            int grow = row0 + ar;
            if (grow < M)
                av = *(const float4*)(A + (size_t)grow * K + k0 + ac4 * 4);
            As[ac4 * 4 + 0][ar] = av.x;
            As[ac4 * 4 + 1][ar] = av.y;
            As[ac4 * 4 + 2][ar] = av.z;
            As[ac4 * 4 + 3][ar] = av.w;
            // B tile: 16 rows x 128 cols = 512 float4
            int br = f >> 5, bc4 = f & 31;
            float4 bv = *(const float4*)(B + (size_t)(k0 + br) * 128 + bc4 * 4);
            *(float4*)&Bs[br][bc4 * 4] = bv;
        }
        __syncthreads();

#pragma unroll
        for (int kk = 0; kk < 16; kk++) {
            float a[8], b[8];
#pragma unroll
            for (int i = 0; i < 8; i++) a[i] = As[kk][ty * 8 + i];
#pragma unroll
            for (int j = 0; j < 8; j++) b[j] = Bs[kk][tx * 8 + j];
#pragma unroll
            for (int i = 0; i < 8; i++)
#pragma unroll
                for (int j = 0; j < 8; j++) acc[i][j] = fmaf(a[i], b[j], acc[i][j]);
        }
        __syncthreads();
    }

#pragma unroll
    for (int i = 0; i < 8; i++) {
        int grow = row0 + ty * 8 + i;
        if (grow < M) {
#pragma unroll
            for (int j = 0; j < 8; j += 4) {
                float4 v = make_float4(acc[i][j], acc[i][j + 1], acc[i][j + 2], acc[i][j + 3]);
                *(float4*)(C + (size_t)grow * 128 + tx * 8 + j) = v;
            }
        }
    }
}

// ---------------------------------------------------------------------------
// SpMM (d=128): one warp per edge. Lane handles 4 consecutive cols (float4).
// agg[dst] += w * support[src] via vector RED.
// ---------------------------------------------------------------------------
__device__ __forceinline__ void red_add_v4(float* p, float4 v) {
    asm volatile(
        "{ .reg .u64 a; cvta.to.global.u64 a, %0;\n\t"
        "  red.global.add.v4.f32 [a], {%1,%2,%3,%4}; }"
        :: "l"(p), "f"(v.x), "f"(v.y), "f"(v.z), "f"(v.w) : "memory");
}

__global__ __launch_bounds__(256)
void spmm128(const float* __restrict__ sup, const int* __restrict__ src,
             const int* __restrict__ dst, const float* __restrict__ w,
             float* __restrict__ agg, int nE) {
    int e = (int)((blockIdx.x * (unsigned)blockDim.x + threadIdx.x) >> 5);
    if (e >= nE) return;
    int lane = threadIdx.x & 31;
    int s = __ldg(src + e);
    int d = __ldg(dst + e);
    float wt = __ldg(w + e);
    float4 v = *(const float4*)(sup + (size_t)s * 128 + lane * 4);
    v.x *= wt; v.y *= wt; v.z *= wt; v.w *= wt;
    red_add_v4(agg + (size_t)d * 128 + lane * 4, v);
}

// ---------------------------------------------------------------------------
// Column sums of a [N,128] matrix into csum[128].
// ---------------------------------------------------------------------------
__global__ __launch_bounds__(256)
void colsum128(const float* __restrict__ h, float* __restrict__ csum, int N) {
    __shared__ float sm[8][128];
    int lane = threadIdx.x & 31, warp = threadIdx.x >> 5;
    float4 acc = make_float4(0.f, 0.f, 0.f, 0.f);
    for (int row = blockIdx.x * 8 + warp; row < N; row += gridDim.x * 8) {
        float4 v = *(const float4*)(h + (size_t)row * 128 + lane * 4);
        acc.x += v.x; acc.y += v.y; acc.z += v.z; acc.w += v.w;
    }
    *(float4*)&sm[warp][lane * 4] = acc;
    __syncthreads();
    if (threadIdx.x < 128) {
        float s = 0.f;
#pragma unroll
        for (int i = 0; i < 8; i++) s += sm[i][threadIdx.x];
        atomicAdd(&csum[threadIdx.x], s);
    }
}

// ---------------------------------------------------------------------------
// enc1 = relu((agg - colmean) / sqrt(eps + rowss))   — warp per row, d=128
// ---------------------------------------------------------------------------
__global__ __launch_bounds__(256)
void pairnorm_relu128(const float* __restrict__ agg, const float* __restrict__ csum,
                      float* __restrict__ out, int N) {
    int row = (int)((blockIdx.x * (unsigned)blockDim.x + threadIdx.x) >> 5);
    if (row >= N) return;
    int lane = threadIdx.x & 31;
    float invN = 1.0f / (float)N;
    float4 mu = *(const float4*)(csum + lane * 4);
    float4 v = *(const float4*)(agg + (size_t)row * 128 + lane * 4);
    v.x -= mu.x * invN; v.y -= mu.y * invN; v.z -= mu.z * invN; v.w -= mu.w * invN;
    float ss = v.x * v.x + v.y * v.y + v.z * v.z + v.w * v.w;
#pragma unroll
    for (int o = 16; o; o >>= 1) ss += __shfl_xor_sync(0xffffffffu, ss, o);
    float inv = rsqrtf(1e-6f + ss);
    v.x = fmaxf(v.x * inv, 0.f);
    v.y = fmaxf(v.y * inv, 0.f);
    v.z = fmaxf(v.z * inv, 0.f);
    v.w = fmaxf(v.w * inv, 0.f);
    *(float4*)(out + (size_t)row * 128 + lane * 4) = v;
}

// ---------------------------------------------------------------------------
// Finalize fused layer-2/3 aggregate [N,128]:
//   cols [0,64)   -> PairNorm + softmax -> pool1
//   cols [64,128) -> PairNorm + relu    -> enc2
// Warp per row; lanes 0..15 own the pool half, 16..31 the enc2 half.
// Sub-reductions use xor offsets {8,4,2,1}, which stay within each 16-lane group.
// ---------------------------------------------------------------------------
__global__ __launch_bounds__(256)
void finalize(const float* __restrict__ agg, const float* __restrict__ csum,
              float* __restrict__ enc2_out, float* __restrict__ pool_out, int N) {
    int row = (int)((blockIdx.x * (unsigned)blockDim.x + threadIdx.x) >> 5);
    if (row >= N) return;
    int lane = threadIdx.x & 31;
    float invN = 1.0f / (float)N;
    float4 mu = *(const float4*)(csum + lane * 4);
    float4 v = *(const float4*)(agg + (size_t)row * 128 + lane * 4);
    v.x -= mu.x * invN; v.y -= mu.y * invN; v.z -= mu.z * invN; v.w -= mu.w * invN;

    float ss = v.x * v.x + v.y * v.y + v.z * v.z + v.w * v.w;
#pragma unroll
    for (int o = 8; o; o >>= 1) ss += __shfl_xor_sync(0xffffffffu, ss, o);
    float inv = rsqrtf(1e-6f + ss);
    v.x *= inv; v.y *= inv; v.z *= inv; v.w *= inv;

    // softmax path (only meaningful for lanes < 16, computed convergent everywhere)
    float mx = fmaxf(fmaxf(v.x, v.y), fmaxf(v.z, v.w));
#pragma unroll
    for (int o = 8; o; o >>= 1) mx = fmaxf(mx, __shfl_xor_sync(0xffffffffu, mx, o));
    float e0 = __expf(v.x - mx), e1 = __expf(v.y - mx);
    float e2 = __expf(v.z - mx), e3 = __expf(v.w - mx);
    float esum = e0 + e1 + e2 + e3;
#pragma unroll
    for (int o = 8; o; o >>= 1) esum += __shfl_xor_sync(0xffffffffu, esum, o);
    float einv = 1.0f / esum;

    if (lane < 16) {
        float4 r = make_float4(e0 * einv, e1 * einv, e2 * einv, e3 * einv);
        *(float4*)(pool_out + (size_t)row * 64 + lane * 4) = r;
    } else {
        float4 r = make_float4(fmaxf(v.x, 0.f), fmaxf(v.y, 0.f),
                               fmaxf(v.z, 0.f), fmaxf(v.w, 0.f));
        *(float4*)(enc2_out + (size_t)row * 64 + (lane - 16) * 4) = r;
    }
}

// ---------------------------------------------------------------------------
// Launch
// ---------------------------------------------------------------------------
extern "C" void kernel_launch(void* const* d_in, const int* in_sizes, int n_in,
                              void* d_out, int out_size) {
    const float* x   = (const float*)d_in[0];
    const int*   src = (const int*)d_in[1];
    const int*   dst = (const int*)d_in[2];
    const float* ew  = (const float*)d_in[3];
    const float* w1  = (const float*)d_in[4];
    // d_in[5] = b1, d_in[7] = bp, d_in[9] = b2: biases cancel under PairNorm centering
    const float* wp  = (const float*)d_in[6];
    const float* w2  = (const float*)d_in[8];
    float* out = (float*)d_out;

    const int N = in_sizes[0] / 256;   // 100000
    const int E = in_sizes[1];         // 1600000

    float *buf1, *buf2, *buf3, *wcat, *csum;
    cudaGetSymbolAddress((void**)&buf1, g_buf1);
    cudaGetSymbolAddress((void**)&buf2, g_buf2);
    cudaGetSymbolAddress((void**)&buf3, g_buf3);
    cudaGetSymbolAddress((void**)&wcat, g_wcat);
    cudaGetSymbolAddress((void**)&csum, g_csum);

    float* enc2_out = out;                      // [N, 64] first (reference return order)
    float* pool_out = out + (size_t)N * 64;     // [N, 64] second

    const int n4 = N * 32;                  // N*128/4 float4s
    const int zgrid = (n4 + 255) / 256;
    const int wgrid = (N + 7) / 8;          // warp-per-row kernels
    const int egrid = (E + 7) / 8;          // warp-per-edge

    // stage 0: clear reduction buffers + pack fused weights
    zero_small<<<1, 256>>>(csum, 256);
    pack_w<<<32, 256>>>(wp, w2, wcat);

    // stage 1: support1 = x @ w1
    sgemm_n128<<<(N + 127) / 128, 256>>>(x, w1, buf1, N, 256);

    // stage 2: agg1 = A @ support1
    zero_f4<<<zgrid, 256>>>((float4*)buf2, n4);
    spmm128<<<egrid, 256>>>(buf1, src, dst, ew, buf2, E);

    // stage 3: enc1 = relu(PairNorm(agg1))  (into buf1)
    colsum128<<<256, 256>>>(buf2, csum, N);
    pairnorm_relu128<<<wgrid, 256>>>(buf2, csum, buf1, N);

    // stage 4: supportB = enc1 @ [wp|w2]  (into buf2)
    sgemm_n128<<<(N + 127) / 128, 256>>>(buf1, wcat, buf2, N, 128);

    // stage 5: aggB = A @ supportB
    zero_f4<<<zgrid, 256>>>((float4*)buf3, n4);
    spmm128<<<egrid, 256>>>(buf2, src, dst, ew, buf3, E);

    // stage 6: pool1 = softmax(PN(aggB[:, :64])), enc2 = relu(PN(aggB[:, 64:]))
    colsum128<<<256, 256>>>(buf3, csum + 128, N);
    finalize<<<wgrid, 256>>>(buf3, csum + 128, enc2_out, pool_out, N);
}

// round 6
// speedup vs baseline: 1.4837x; 1.4837x over previous
#include <cuda_runtime.h>
#include <cuda_bf16.h>
#include <math.h>

// ---------------------------------------------------------------------------
// GCNEncoder: enc1 = relu(PN(A @ (x@w1)));
//             pool1 = softmax(PN(A @ (enc1@wp)));  enc2 = relu(PN(A @ (enc1@w2)))
// Biases cancel under PairNorm centering. Layers 2/3 fused into one 128-wide
// GEMM + one 128-wide SpMM. SpMM is CSR gather-reduce (no scatter atomics):
// CSR built per-launch via histogram -> scan -> permute (graph-capturable).
// ---------------------------------------------------------------------------

#define N_NODES_MAX 100000
#define NB_SCAN 98            // ceil(100000/1024)

__device__ float g_buf1[(size_t)N_NODES_MAX * 128]; // support1, then enc1
__device__ float g_buf2[(size_t)N_NODES_MAX * 128]; // agg1, then supportB
__device__ float g_buf3[(size_t)N_NODES_MAX * 128]; // aggB
__device__ float g_wcat[128 * 128];                 // [wp | w2]
__device__ float g_csum[256];                       // col sums (stage1 / stage2)
// CSR scratch
__device__ int  g_cnt[N_NODES_MAX];
__device__ int  g_scan[N_NODES_MAX];
__device__ int  g_bsum[NB_SCAN];
__device__ int  g_rowptr[N_NODES_MAX + 1];
__device__ int  g_wcur[N_NODES_MAX];
__device__ int2 g_perm[1600000];                    // {src, weight-bits} sorted by dst

// ---------------------------------------------------------------------------
// Setup: zero counters + colsum buffers
// ---------------------------------------------------------------------------
__global__ void zero_setup(int* cnt, float* csum, int N) {
    int i = blockIdx.x * blockDim.x + threadIdx.x;
    if (i < N) cnt[i] = 0;
    if (i < 256) csum[i] = 0.f;
}

// ---------------------------------------------------------------------------
// Pack wcat = [wp | w2]   (wp, w2: [128, 64] row-major)
// ---------------------------------------------------------------------------
__global__ void pack_w(const float* __restrict__ wp, const float* __restrict__ w2,
                       float* __restrict__ wcat) {
    int i = blockIdx.x * blockDim.x + threadIdx.x;
    if (i >= 128 * 64) return;
    int r = i >> 6, c = i & 63;
    wcat[r * 128 + c]      = wp[i];
    wcat[r * 128 + 64 + c] = w2[i];
}

// ---------------------------------------------------------------------------
// CSR build: histogram of dst, exclusive scan, permutation scatter
// ---------------------------------------------------------------------------
__global__ void hist_dst(const int* __restrict__ dst, int* __restrict__ cnt, int E) {
    int e = blockIdx.x * blockDim.x + threadIdx.x;
    if (e < E) atomicAdd(&cnt[dst[e]], 1);
}

__global__ void scan1(const int* __restrict__ cnt, int* __restrict__ scan_out,
                      int* __restrict__ bsum, int N) {
    __shared__ int sm[1024];
    int i = blockIdx.x * 1024 + threadIdx.x;
    sm[threadIdx.x] = (i < N) ? cnt[i] : 0;
    __syncthreads();
    for (int o = 1; o < 1024; o <<= 1) {
        int t = (threadIdx.x >= o) ? sm[threadIdx.x - o] : 0;
        __syncthreads();
        sm[threadIdx.x] += t;
        __syncthreads();
    }
    if (i < N) scan_out[i] = sm[threadIdx.x];
    if (threadIdx.x == 1023) bsum[blockIdx.x] = sm[1023];
}

__global__ void scan2(int* bsum, int nb) {        // exclusive, in place (tiny)
    if (threadIdx.x == 0) {
        int run = 0;
        for (int b = 0; b < nb; b++) { int t = bsum[b]; bsum[b] = run; run += t; }
    }
}

__global__ void scan3(const int* __restrict__ scan_in, const int* __restrict__ cnt,
                      const int* __restrict__ bsum, int* __restrict__ rowptr,
                      int* __restrict__ wcur, int N, int E) {
    int i = blockIdx.x * 1024 + threadIdx.x;
    if (i < N) {
        int ex = scan_in[i] - cnt[i] + bsum[blockIdx.x];  // exclusive prefix
        rowptr[i] = ex;
        wcur[i]   = ex;
    }
    if (i == N - 1) rowptr[N] = E;
}

__global__ void scatter_perm(const int* __restrict__ src, const int* __restrict__ dst,
                             const float* __restrict__ ew, int* __restrict__ wcur,
                             int2* __restrict__ perm, int E) {
    int e = blockIdx.x * blockDim.x + threadIdx.x;
    if (e >= E) return;
    int p = atomicAdd(&wcur[dst[e]], 1);
    perm[p] = make_int2(src[e], __float_as_int(ew[e]));
}

// ---------------------------------------------------------------------------
// SGEMM: C[M,128] = A[M,K] @ B[K,128].  BM=128, BN=128, BK=16, 256 threads,
// 8x8 register tiles. K multiple of 16.
// ---------------------------------------------------------------------------
__global__ __launch_bounds__(256, 2)
void sgemm_n128(const float* __restrict__ A, const float* __restrict__ B,
                float* __restrict__ C, int M, int K) {
    __shared__ float As[16][128];
    __shared__ float Bs[16][128];

    const int tid = threadIdx.x;
    const int row0 = blockIdx.x * 128;
    const int tx = tid & 15;
    const int ty = tid >> 4;

    float acc[8][8];
#pragma unroll
    for (int i = 0; i < 8; i++)
#pragma unroll
        for (int j = 0; j < 8; j++) acc[i][j] = 0.f;

    for (int k0 = 0; k0 < K; k0 += 16) {
#pragma unroll
        for (int it = 0; it < 2; it++) {
            int f = tid + it * 256;
            int ar = f >> 2, ac4 = f & 3;
            float4 av = make_float4(0.f, 0.f, 0.f, 0.f);
            int grow = row0 + ar;
            if (grow < M)
                av = *(const float4*)(A + (size_t)grow * K + k0 + ac4 * 4);
            As[ac4 * 4 + 0][ar] = av.x;
            As[ac4 * 4 + 1][ar] = av.y;
            As[ac4 * 4 + 2][ar] = av.z;
            As[ac4 * 4 + 3][ar] = av.w;
            int br = f >> 5, bc4 = f & 31;
            float4 bv = *(const float4*)(B + (size_t)(k0 + br) * 128 + bc4 * 4);
            *(float4*)&Bs[br][bc4 * 4] = bv;
        }
        __syncthreads();

#pragma unroll
        for (int kk = 0; kk < 16; kk++) {
            float a[8], b[8];
#pragma unroll
            for (int i = 0; i < 8; i++) a[i] = As[kk][ty * 8 + i];
#pragma unroll
            for (int j = 0; j < 8; j++) b[j] = Bs[kk][tx * 8 + j];
#pragma unroll
            for (int i = 0; i < 8; i++)
#pragma unroll
                for (int j = 0; j < 8; j++) acc[i][j] = fmaf(a[i], b[j], acc[i][j]);
        }
        __syncthreads();
    }

#pragma unroll
    for (int i = 0; i < 8; i++) {
        int grow = row0 + ty * 8 + i;
        if (grow < M) {
#pragma unroll
            for (int j = 0; j < 8; j += 4) {
                float4 v = make_float4(acc[i][j], acc[i][j + 1], acc[i][j + 2], acc[i][j + 3]);
                *(float4*)(C + (size_t)grow * 128 + tx * 8 + j) = v;
            }
        }
    }
}

// ---------------------------------------------------------------------------
// SpMM CSR gather-reduce (d=128): warp per node (grid-stride). Lane owns 4
// consecutive columns. Row accumulates in registers -> single streaming store.
// Column sums fused into the epilogue (block reduce + 128 atomics per block).
// ---------------------------------------------------------------------------
__global__ __launch_bounds__(256)
void spmm_csr(const float* __restrict__ sup, const int* __restrict__ rowptr,
              const int2* __restrict__ perm, float* __restrict__ agg,
              float* __restrict__ csum, int N) {
    const int lane = threadIdx.x & 31;
    const int wid  = threadIdx.x >> 5;
    const int gwarp  = blockIdx.x * 8 + wid;
    const int stride = gridDim.x * 8;

    float4 cs = make_float4(0.f, 0.f, 0.f, 0.f);

    for (int node = gwarp; node < N; node += stride) {
        int beg = __ldg(rowptr + node);
        int end = __ldg(rowptr + node + 1);
        float4 acc = make_float4(0.f, 0.f, 0.f, 0.f);
        for (int i = beg; i < end; i += 32) {
            int n = min(32, end - i);
            int2 ewp = (lane < n) ? __ldg(perm + i + lane) : make_int2(0, 0);
#pragma unroll 4
            for (int j = 0; j < n; j++) {
                int   s = __shfl_sync(0xffffffffu, ewp.x, j);
                float w = __int_as_float(__shfl_sync(0xffffffffu, ewp.y, j));
                float4 v = *(const float4*)(sup + (size_t)s * 128 + lane * 4);
                acc.x = fmaf(w, v.x, acc.x);
                acc.y = fmaf(w, v.y, acc.y);
                acc.z = fmaf(w, v.z, acc.z);
                acc.w = fmaf(w, v.w, acc.w);
            }
        }
        *(float4*)(agg + (size_t)node * 128 + lane * 4) = acc;
        cs.x += acc.x; cs.y += acc.y; cs.z += acc.z; cs.w += acc.w;
    }

    __shared__ float sm[8][128];
    *(float4*)&sm[wid][lane * 4] = cs;
    __syncthreads();
    if (threadIdx.x < 128) {
        float s = 0.f;
#pragma unroll
        for (int i = 0; i < 8; i++) s += sm[i][threadIdx.x];
        atomicAdd(&csum[threadIdx.x], s);
    }
}

// ---------------------------------------------------------------------------
// enc1 = relu((agg - colmean) / sqrt(eps + rowss))   — warp per row
// ---------------------------------------------------------------------------
__global__ __launch_bounds__(256)
void pairnorm_relu128(const float* __restrict__ agg, const float* __restrict__ csum,
                      float* __restrict__ out, int N) {
    int row = (int)((blockIdx.x * (unsigned)blockDim.x + threadIdx.x) >> 5);
    if (row >= N) return;
    int lane = threadIdx.x & 31;
    float invN = 1.0f / (float)N;
    float4 mu = *(const float4*)(csum + lane * 4);
    float4 v = *(const float4*)(agg + (size_t)row * 128 + lane * 4);
    v.x -= mu.x * invN; v.y -= mu.y * invN; v.z -= mu.z * invN; v.w -= mu.w * invN;
    float ss = v.x * v.x + v.y * v.y + v.z * v.z + v.w * v.w;
#pragma unroll
    for (int o = 16; o; o >>= 1) ss += __shfl_xor_sync(0xffffffffu, ss, o);
    float inv = rsqrtf(1e-6f + ss);
    v.x = fmaxf(v.x * inv, 0.f);
    v.y = fmaxf(v.y * inv, 0.f);
    v.z = fmaxf(v.z * inv, 0.f);
    v.w = fmaxf(v.w * inv, 0.f);
    *(float4*)(out + (size_t)row * 128 + lane * 4) = v;
}

// ---------------------------------------------------------------------------
// Finalize fused layer-2/3 aggregate [N,128]:
//   cols [0,64)   -> PairNorm + softmax -> pool1
//   cols [64,128) -> PairNorm + relu    -> enc2
// Sub-reductions (xor 8,4,2,1) stay inside each 16-lane half.
// ---------------------------------------------------------------------------
__global__ __launch_bounds__(256)
void finalize(const float* __restrict__ agg, const float* __restrict__ csum,
              float* __restrict__ enc2_out, float* __restrict__ pool_out, int N) {
    int row = (int)((blockIdx.x * (unsigned)blockDim.x + threadIdx.x) >> 5);
    if (row >= N) return;
    int lane = threadIdx.x & 31;
    float invN = 1.0f / (float)N;
    float4 mu = *(const float4*)(csum + lane * 4);
    float4 v = *(const float4*)(agg + (size_t)row * 128 + lane * 4);
    v.x -= mu.x * invN; v.y -= mu.y * invN; v.z -= mu.z * invN; v.w -= mu.w * invN;

    float ss = v.x * v.x + v.y * v.y + v.z * v.z + v.w * v.w;
#pragma unroll
    for (int o = 8; o; o >>= 1) ss += __shfl_xor_sync(0xffffffffu, ss, o);
    float inv = rsqrtf(1e-6f + ss);
    v.x *= inv; v.y *= inv; v.z *= inv; v.w *= inv;

    float mx = fmaxf(fmaxf(v.x, v.y), fmaxf(v.z, v.w));
#pragma unroll
    for (int o = 8; o; o >>= 1) mx = fmaxf(mx, __shfl_xor_sync(0xffffffffu, mx, o));
    float e0 = __expf(v.x - mx), e1 = __expf(v.y - mx);
    float e2 = __expf(v.z - mx), e3 = __expf(v.w - mx);
    float esum = e0 + e1 + e2 + e3;
#pragma unroll
    for (int o = 8; o; o >>= 1) esum += __shfl_xor_sync(0xffffffffu, esum, o);
    float einv = 1.0f / esum;

    if (lane < 16) {
        float4 r = make_float4(e0 * einv, e1 * einv, e2 * einv, e3 * einv);
        *(float4*)(pool_out + (size_t)row * 64 + lane * 4) = r;
    } else {
        float4 r = make_float4(fmaxf(v.x, 0.f), fmaxf(v.y, 0.f),
                               fmaxf(v.z, 0.f), fmaxf(v.w, 0.f));
        *(float4*)(enc2_out + (size_t)row * 64 + (lane - 16) * 4) = r;
    }
}

// ---------------------------------------------------------------------------
// Launch
// ---------------------------------------------------------------------------
extern "C" void kernel_launch(void* const* d_in, const int* in_sizes, int n_in,
                              void* d_out, int out_size) {
    const float* x   = (const float*)d_in[0];
    const int*   src = (const int*)d_in[1];
    const int*   dst = (const int*)d_in[2];
    const float* ew  = (const float*)d_in[3];
    const float* w1  = (const float*)d_in[4];
    // d_in[5]=b1, d_in[7]=bp, d_in[9]=b2 cancel under PairNorm centering
    const float* wp  = (const float*)d_in[6];
    const float* w2  = (const float*)d_in[8];
    float* out = (float*)d_out;

    const int N = in_sizes[0] / 256;   // 100000
    const int E = in_sizes[1];         // 1600000

    float *buf1, *buf2, *buf3, *wcat, *csum;
    int *cnt, *scn, *bsum, *rowptr, *wcur;
    int2 *perm;
    cudaGetSymbolAddress((void**)&buf1, g_buf1);
    cudaGetSymbolAddress((void**)&buf2, g_buf2);
    cudaGetSymbolAddress((void**)&buf3, g_buf3);
    cudaGetSymbolAddress((void**)&wcat, g_wcat);
    cudaGetSymbolAddress((void**)&csum, g_csum);
    cudaGetSymbolAddress((void**)&cnt, g_cnt);
    cudaGetSymbolAddress((void**)&scn, g_scan);
    cudaGetSymbolAddress((void**)&bsum, g_bsum);
    cudaGetSymbolAddress((void**)&rowptr, g_rowptr);
    cudaGetSymbolAddress((void**)&wcur, g_wcur);
    cudaGetSymbolAddress((void**)&perm, g_perm);

    float* enc2_out = out;                      // [N, 64] (reference return order)
    float* pool_out = out + (size_t)N * 64;     // [N, 64]

    const int wgrid = (N + 7) / 8;              // warp-per-row kernels
    const int egrid = (E + 255) / 256;          // thread-per-edge kernels
    const int sgrid = 148 * 8;                  // grid-stride spmm (8 blocks/SM)
    const int nbs   = (N + 1023) / 1024;        // scan blocks (== NB_SCAN)

    // ---- CSR build (once, used by both SpMMs) ----
    zero_setup<<<(N + 255) / 256, 256>>>(cnt, csum, N);
    pack_w<<<32, 256>>>(wp, w2, wcat);
    hist_dst<<<egrid, 256>>>(dst, cnt, E);
    scan1<<<nbs, 1024>>>(cnt, scn, bsum, N);
    scan2<<<1, 32>>>(bsum, nbs);
    scan3<<<nbs, 1024>>>(scn, cnt, bsum, rowptr, wcur, N, E);
    scatter_perm<<<egrid, 256>>>(src, dst, ew, wcur, perm, E);

    // ---- stage 1: support1 = x @ w1 ----
    sgemm_n128<<<(N + 127) / 128, 256>>>(x, w1, buf1, N, 256);

    // ---- stage 2: agg1 = A @ support1 (+ fused colsum) ----
    spmm_csr<<<sgrid, 256>>>(buf1, rowptr, perm, buf2, csum, N);

    // ---- stage 3: enc1 = relu(PairNorm(agg1)) ----
    pairnorm_relu128<<<wgrid, 256>>>(buf2, csum, buf1, N);

    // ---- stage 4: supportB = enc1 @ [wp|w2] ----
    sgemm_n128<<<(N + 127) / 128, 256>>>(buf1, wcat, buf2, N, 128);

    // ---- stage 5: aggB = A @ supportB (+ fused colsum) ----
    spmm_csr<<<sgrid, 256>>>(buf2, rowptr, perm, buf3, csum + 128, N);

    // ---- stage 6: pool1 = softmax(PN(:,:64)), enc2 = relu(PN(:,64:)) ----
    finalize<<<wgrid, 256>>>(buf3, csum + 128, enc2_out, pool_out, N);
}

// round 7
// speedup vs baseline: 1.7008x; 1.1463x over previous
#include <cuda_runtime.h>
#include <cuda_bf16.h>
#include <cuda_fp16.h>
#include <math.h>

// ---------------------------------------------------------------------------
// GCNEncoder: enc1 = relu(PN(A @ (x@w1)));
//             pool1 = softmax(PN(A @ (enc1@wp)));  enc2 = relu(PN(A @ (enc1@w2)))
// Biases cancel under PairNorm. Layers 2/3 fused (128-wide GEMM + SpMM).
// SpMM: CSR gather-reduce, gather operand stored fp16 (halves L2 traffic);
// all accumulation fp32.
// ---------------------------------------------------------------------------

#define N_NODES_MAX 100000
#define NB_SCAN 98            // ceil(100000/1024)

__device__ float  g_buf1[(size_t)N_NODES_MAX * 128]; // agg1 / enc1
__device__ float  g_buf2[(size_t)N_NODES_MAX * 128]; // agg1 stage, aggB
__device__ __half g_hsup[(size_t)N_NODES_MAX * 128]; // fp16 support (both stages)
__device__ float  g_wcat[128 * 128];                 // [wp | w2]
__device__ float  g_csum[256];                       // col sums (stage1 / stage2)
// CSR scratch
__device__ int  g_cnt[N_NODES_MAX];
__device__ int  g_scan[N_NODES_MAX];
__device__ int  g_bsum[NB_SCAN];
__device__ int  g_rowptr[N_NODES_MAX + 1];
__device__ int  g_wcur[N_NODES_MAX];
__device__ int2 g_perm[1600000];                     // {src, weight-bits} by dst

// ---------------------------------------------------------------------------
__global__ void zero_setup(int* cnt, float* csum, int N) {
    int i = blockIdx.x * blockDim.x + threadIdx.x;
    if (i < N) cnt[i] = 0;
    if (i < 256) csum[i] = 0.f;
}

__global__ void pack_w(const float* __restrict__ wp, const float* __restrict__ w2,
                       float* __restrict__ wcat) {
    int i = blockIdx.x * blockDim.x + threadIdx.x;
    if (i >= 128 * 64) return;
    int r = i >> 6, c = i & 63;
    wcat[r * 128 + c]      = wp[i];
    wcat[r * 128 + 64 + c] = w2[i];
}

// ---------------------------------------------------------------------------
// CSR build: histogram of dst, exclusive scan, permutation scatter
// ---------------------------------------------------------------------------
__global__ void hist_dst(const int* __restrict__ dst, int* __restrict__ cnt, int E) {
    int e = blockIdx.x * blockDim.x + threadIdx.x;
    if (e < E) atomicAdd(&cnt[dst[e]], 1);
}

__global__ void scan1(const int* __restrict__ cnt, int* __restrict__ scan_out,
                      int* __restrict__ bsum, int N) {
    __shared__ int sm[1024];
    int i = blockIdx.x * 1024 + threadIdx.x;
    sm[threadIdx.x] = (i < N) ? cnt[i] : 0;
    __syncthreads();
    for (int o = 1; o < 1024; o <<= 1) {
        int t = (threadIdx.x >= o) ? sm[threadIdx.x - o] : 0;
        __syncthreads();
        sm[threadIdx.x] += t;
        __syncthreads();
    }
    if (i < N) scan_out[i] = sm[threadIdx.x];
    if (threadIdx.x == 1023) bsum[blockIdx.x] = sm[1023];
}

__global__ void scan2(int* bsum, int nb) {
    if (threadIdx.x == 0) {
        int run = 0;
        for (int b = 0; b < nb; b++) { int t = bsum[b]; bsum[b] = run; run += t; }
    }
}

__global__ void scan3(const int* __restrict__ scan_in, const int* __restrict__ cnt,
                      const int* __restrict__ bsum, int* __restrict__ rowptr,
                      int* __restrict__ wcur, int N, int E) {
    int i = blockIdx.x * 1024 + threadIdx.x;
    if (i < N) {
        int ex = scan_in[i] - cnt[i] + bsum[blockIdx.x];
        rowptr[i] = ex;
        wcur[i]   = ex;
    }
    if (i == N - 1) rowptr[N] = E;
}

__global__ void scatter_perm(const int* __restrict__ src, const int* __restrict__ dst,
                             const float* __restrict__ ew, int* __restrict__ wcur,
                             int2* __restrict__ perm, int E) {
    int e = blockIdx.x * blockDim.x + threadIdx.x;
    if (e >= E) return;
    int p = atomicAdd(&wcur[dst[e]], 1);
    perm[p] = make_int2(src[e], __float_as_int(ew[e]));
}

// ---------------------------------------------------------------------------
// SGEMM: C[M,128] = A[M,K] @ B[K,128] (fp32 math), output stored as fp16.
// BM=128, BN=128, BK=16, 256 threads, 8x8 register tiles.
// ---------------------------------------------------------------------------
__global__ __launch_bounds__(256, 2)
void sgemm_n128_h(const float* __restrict__ A, const float* __restrict__ B,
                  __half* __restrict__ C, int M, int K) {
    __shared__ float As[16][128];
    __shared__ float Bs[16][128];

    const int tid = threadIdx.x;
    const int row0 = blockIdx.x * 128;
    const int tx = tid & 15;
    const int ty = tid >> 4;

    float acc[8][8];
#pragma unroll
    for (int i = 0; i < 8; i++)
#pragma unroll
        for (int j = 0; j < 8; j++) acc[i][j] = 0.f;

    for (int k0 = 0; k0 < K; k0 += 16) {
#pragma unroll
        for (int it = 0; it < 2; it++) {
            int f = tid + it * 256;
            int ar = f >> 2, ac4 = f & 3;
            float4 av = make_float4(0.f, 0.f, 0.f, 0.f);
            int grow = row0 + ar;
            if (grow < M)
                av = *(const float4*)(A + (size_t)grow * K + k0 + ac4 * 4);
            As[ac4 * 4 + 0][ar] = av.x;
            As[ac4 * 4 + 1][ar] = av.y;
            As[ac4 * 4 + 2][ar] = av.z;
            As[ac4 * 4 + 3][ar] = av.w;
            int br = f >> 5, bc4 = f & 31;
            float4 bv = *(const float4*)(B + (size_t)(k0 + br) * 128 + bc4 * 4);
            *(float4*)&Bs[br][bc4 * 4] = bv;
        }
        __syncthreads();

#pragma unroll
        for (int kk = 0; kk < 16; kk++) {
            float a[8], b[8];
#pragma unroll
            for (int i = 0; i < 8; i++) a[i] = As[kk][ty * 8 + i];
#pragma unroll
            for (int j = 0; j < 8; j++) b[j] = Bs[kk][tx * 8 + j];
#pragma unroll
            for (int i = 0; i < 8; i++)
#pragma unroll
                for (int j = 0; j < 8; j++) acc[i][j] = fmaf(a[i], b[j], acc[i][j]);
        }
        __syncthreads();
    }

#pragma unroll
    for (int i = 0; i < 8; i++) {
        int grow = row0 + ty * 8 + i;
        if (grow < M) {
#pragma unroll
            for (int j = 0; j < 8; j += 4) {
                __half2 p0 = __floats2half2_rn(acc[i][j],     acc[i][j + 1]);
                __half2 p1 = __floats2half2_rn(acc[i][j + 2], acc[i][j + 3]);
                uint2 pk;
                pk.x = *reinterpret_cast<unsigned*>(&p0);
                pk.y = *reinterpret_cast<unsigned*>(&p1);
                *(uint2*)(C + (size_t)grow * 128 + tx * 8 + j) = pk;
            }
        }
    }
}

// ---------------------------------------------------------------------------
// SpMM CSR gather-reduce (d=128): warp per node (grid-stride). Lane owns 4
// consecutive columns (8B fp16 gather). fp32 accumulation in registers ->
// single streaming store. Column sums fused into the epilogue.
// ---------------------------------------------------------------------------
__global__ __launch_bounds__(256)
void spmm_csr_h(const __half* __restrict__ sup, const int* __restrict__ rowptr,
                const int2* __restrict__ perm, float* __restrict__ agg,
                float* __restrict__ csum, int N) {
    const int lane = threadIdx.x & 31;
    const int wid  = threadIdx.x >> 5;
    const int gwarp  = blockIdx.x * 8 + wid;
    const int stride = gridDim.x * 8;

    float4 cs = make_float4(0.f, 0.f, 0.f, 0.f);

    for (int node = gwarp; node < N; node += stride) {
        int beg = __ldg(rowptr + node);
        int end = __ldg(rowptr + node + 1);
        float4 acc = make_float4(0.f, 0.f, 0.f, 0.f);
        for (int i = beg; i < end; i += 32) {
            int n = min(32, end - i);
            int2 ewp = (lane < n) ? __ldg(perm + i + lane) : make_int2(0, 0);
#pragma unroll 4
            for (int j = 0; j < n; j++) {
                int   s = __shfl_sync(0xffffffffu, ewp.x, j);
                float w = __int_as_float(__shfl_sync(0xffffffffu, ewp.y, j));
                uint2 raw = *(const uint2*)(sup + (size_t)s * 128 + lane * 4);
                __half2 h0 = *reinterpret_cast<__half2*>(&raw.x);
                __half2 h1 = *reinterpret_cast<__half2*>(&raw.y);
                float2 f0 = __half22float2(h0);
                float2 f1 = __half22float2(h1);
                acc.x = fmaf(w, f0.x, acc.x);
                acc.y = fmaf(w, f0.y, acc.y);
                acc.z = fmaf(w, f1.x, acc.z);
                acc.w = fmaf(w, f1.y, acc.w);
            }
        }
        *(float4*)(agg + (size_t)node * 128 + lane * 4) = acc;
        cs.x += acc.x; cs.y += acc.y; cs.z += acc.z; cs.w += acc.w;
    }

    __shared__ float sm[8][128];
    *(float4*)&sm[wid][lane * 4] = cs;
    __syncthreads();
    if (threadIdx.x < 128) {
        float s = 0.f;
#pragma unroll
        for (int i = 0; i < 8; i++) s += sm[i][threadIdx.x];
        atomicAdd(&csum[threadIdx.x], s);
    }
}

// ---------------------------------------------------------------------------
// enc1 = relu((agg - colmean) / sqrt(eps + rowss))   — warp per row (fp32 out)
// ---------------------------------------------------------------------------
__global__ __launch_bounds__(256)
void pairnorm_relu128(const float* __restrict__ agg, const float* __restrict__ csum,
                      float* __restrict__ out, int N) {
    int row = (int)((blockIdx.x * (unsigned)blockDim.x + threadIdx.x) >> 5);
    if (row >= N) return;
    int lane = threadIdx.x & 31;
    float invN = 1.0f / (float)N;
    float4 mu = *(const float4*)(csum + lane * 4);
    float4 v = *(const float4*)(agg + (size_t)row * 128 + lane * 4);
    v.x -= mu.x * invN; v.y -= mu.y * invN; v.z -= mu.z * invN; v.w -= mu.w * invN;
    float ss = v.x * v.x + v.y * v.y + v.z * v.z + v.w * v.w;
#pragma unroll
    for (int o = 16; o; o >>= 1) ss += __shfl_xor_sync(0xffffffffu, ss, o);
    float inv = rsqrtf(1e-6f + ss);
    v.x = fmaxf(v.x * inv, 0.f);
    v.y = fmaxf(v.y * inv, 0.f);
    v.z = fmaxf(v.z * inv, 0.f);
    v.w = fmaxf(v.w * inv, 0.f);
    *(float4*)(out + (size_t)row * 128 + lane * 4) = v;
}

// ---------------------------------------------------------------------------
// Finalize fused layer-2/3 aggregate [N,128]:
//   cols [0,64)  -> PN + softmax -> pool1 ; cols [64,128) -> PN + relu -> enc2
// Sub-reductions (xor 8,4,2,1) stay inside each 16-lane half.
// ---------------------------------------------------------------------------
__global__ __launch_bounds__(256)
void finalize(const float* __restrict__ agg, const float* __restrict__ csum,
              float* __restrict__ enc2_out, float* __restrict__ pool_out, int N) {
    int row = (int)((blockIdx.x * (unsigned)blockDim.x + threadIdx.x) >> 5);
    if (row >= N) return;
    int lane = threadIdx.x & 31;
    float invN = 1.0f / (float)N;
    float4 mu = *(const float4*)(csum + lane * 4);
    float4 v = *(const float4*)(agg + (size_t)row * 128 + lane * 4);
    v.x -= mu.x * invN; v.y -= mu.y * invN; v.z -= mu.z * invN; v.w -= mu.w * invN;

    float ss = v.x * v.x + v.y * v.y + v.z * v.z + v.w * v.w;
#pragma unroll
    for (int o = 8; o; o >>= 1) ss += __shfl_xor_sync(0xffffffffu, ss, o);
    float inv = rsqrtf(1e-6f + ss);
    v.x *= inv; v.y *= inv; v.z *= inv; v.w *= inv;

    float mx = fmaxf(fmaxf(v.x, v.y), fmaxf(v.z, v.w));
#pragma unroll
    for (int o = 8; o; o >>= 1) mx = fmaxf(mx, __shfl_xor_sync(0xffffffffu, mx, o));
    float e0 = __expf(v.x - mx), e1 = __expf(v.y - mx);
    float e2 = __expf(v.z - mx), e3 = __expf(v.w - mx);
    float esum = e0 + e1 + e2 + e3;
#pragma unroll
    for (int o = 8; o; o >>= 1) esum += __shfl_xor_sync(0xffffffffu, esum, o);
    float einv = 1.0f / esum;

    if (lane < 16) {
        float4 r = make_float4(e0 * einv, e1 * einv, e2 * einv, e3 * einv);
        *(float4*)(pool_out + (size_t)row * 64 + lane * 4) = r;
    } else {
        float4 r = make_float4(fmaxf(v.x, 0.f), fmaxf(v.y, 0.f),
                               fmaxf(v.z, 0.f), fmaxf(v.w, 0.f));
        *(float4*)(enc2_out + (size_t)row * 64 + (lane - 16) * 4) = r;
    }
}

// ---------------------------------------------------------------------------
// Launch
// ---------------------------------------------------------------------------
extern "C" void kernel_launch(void* const* d_in, const int* in_sizes, int n_in,
                              void* d_out, int out_size) {
    const float* x   = (const float*)d_in[0];
    const int*   src = (const int*)d_in[1];
    const int*   dst = (const int*)d_in[2];
    const float* ew  = (const float*)d_in[3];
    const float* w1  = (const float*)d_in[4];
    // d_in[5]=b1, d_in[7]=bp, d_in[9]=b2 cancel under PairNorm centering
    const float* wp  = (const float*)d_in[6];
    const float* w2  = (const float*)d_in[8];
    float* out = (float*)d_out;

    const int N = in_sizes[0] / 256;   // 100000
    const int E = in_sizes[1];         // 1600000

    float *buf1, *buf2, *wcat, *csum;
    __half* hsup;
    int *cnt, *scn, *bsum, *rowptr, *wcur;
    int2 *perm;
    cudaGetSymbolAddress((void**)&buf1, g_buf1);
    cudaGetSymbolAddress((void**)&buf2, g_buf2);
    cudaGetSymbolAddress((void**)&hsup, g_hsup);
    cudaGetSymbolAddress((void**)&wcat, g_wcat);
    cudaGetSymbolAddress((void**)&csum, g_csum);
    cudaGetSymbolAddress((void**)&cnt, g_cnt);
    cudaGetSymbolAddress((void**)&scn, g_scan);
    cudaGetSymbolAddress((void**)&bsum, g_bsum);
    cudaGetSymbolAddress((void**)&rowptr, g_rowptr);
    cudaGetSymbolAddress((void**)&wcur, g_wcur);
    cudaGetSymbolAddress((void**)&perm, g_perm);

    float* enc2_out = out;                      // [N, 64] (reference return order)
    float* pool_out = out + (size_t)N * 64;     // [N, 64]

    const int wgrid = (N + 7) / 8;              // warp-per-row kernels
    const int egrid = (E + 255) / 256;          // thread-per-edge kernels
    const int sgrid = 148 * 8;                  // grid-stride spmm
    const int nbs   = (N + 1023) / 1024;        // scan blocks

    // ---- CSR build (once, shared by both SpMMs) ----
    zero_setup<<<(N + 255) / 256, 256>>>(cnt, csum, N);
    pack_w<<<32, 256>>>(wp, w2, wcat);
    hist_dst<<<egrid, 256>>>(dst, cnt, E);
    scan1<<<nbs, 1024>>>(cnt, scn, bsum, N);
    scan2<<<1, 32>>>(bsum, nbs);
    scan3<<<nbs, 1024>>>(scn, cnt, bsum, rowptr, wcur, N, E);
    scatter_perm<<<egrid, 256>>>(src, dst, ew, wcur, perm, E);

    // ---- stage 1: support1 = x @ w1 (fp16 out) ----
    sgemm_n128_h<<<(N + 127) / 128, 256>>>(x, w1, hsup, N, 256);

    // ---- stage 2: agg1 = A @ support1 (+ fused colsum) ----
    spmm_csr_h<<<sgrid, 256>>>(hsup, rowptr, perm, buf2, csum, N);

    // ---- stage 3: enc1 = relu(PairNorm(agg1)) (fp32) ----
    pairnorm_relu128<<<wgrid, 256>>>(buf2, csum, buf1, N);

    // ---- stage 4: supportB = enc1 @ [wp|w2] (fp16 out) ----
    sgemm_n128_h<<<(N + 127) / 128, 256>>>(buf1, wcat, hsup, N, 128);

    // ---- stage 5: aggB = A @ supportB (+ fused colsum) ----
    spmm_csr_h<<<sgrid, 256>>>(hsup, rowptr, perm, buf2, csum + 128, N);

    // ---- stage 6: pool1 = softmax(PN(:,:64)), enc2 = relu(PN(:,64:)) ----
    finalize<<<wgrid, 256>>>(buf2, csum + 128, enc2_out, pool_out, N);
}

// round 12
// speedup vs baseline: 2.8013x; 1.6471x over previous
#include <cuda_runtime.h>
#include <cuda_fp16.h>
#include <mma.h>
using namespace nvcuda;

#define NMAX 100000
#define SA 40

__device__ float  g_buf1[(size_t)NMAX*128];
__device__ float  g_buf2[(size_t)NMAX*128];
__device__ __half g_hsup[(size_t)NMAX*128];
__device__ __half g_w1t[128*256];
__device__ __half g_wct[128*128];
__device__ float  g_csum[256];
__device__ int    g_cnt[NMAX];
__device__ int    g_scn[NMAX];
__device__ int    g_bsm[98];
__device__ int    g_rp[NMAX+1];
__device__ int    g_wc[NMAX];
__device__ int2   g_perm[1600000];

__global__ void setup(int* cnt, float* cs, int n) {
  int i = blockIdx.x*blockDim.x + threadIdx.x;
  if (i < n) cnt[i] = 0;
  if (i < 256) cs[i] = 0.f;
}

__global__ void prep(const float* w1, const float* wp, const float* w2,
                     __half* w1t, __half* wct) {
  int i = blockIdx.x*blockDim.x + threadIdx.x;
  if (i < 256*128) { int k = i>>7, n = i&127; w1t[n*256+k] = __float2half(w1[i]); }
  if (i < 128*64) {
    int k = i>>6, c = i&63;
    wct[c*128+k] = __float2half(wp[i]);
    wct[(64+c)*128+k] = __float2half(w2[i]);
  }
}

__global__ void hist(const int* dst, int* cnt, int nE) {
  int e = blockIdx.x*blockDim.x + threadIdx.x;
  if (e < nE) atomicAdd(&cnt[dst[e]], 1);
}

__global__ void scanA(const int* cnt, int* so, int* bs, int n) {
  __shared__ int sm[1024];
  int i = blockIdx.x*1024 + threadIdx.x;
  sm[threadIdx.x] = (i < n) ? cnt[i] : 0;
  __syncthreads();
  for (int o = 1; o < 1024; o <<= 1) {
    int t = (threadIdx.x >= o) ? sm[threadIdx.x-o] : 0;
    __syncthreads();
    sm[threadIdx.x] += t;
    __syncthreads();
  }
  if (i < n) so[i] = sm[threadIdx.x];
  if (threadIdx.x == 1023) bs[blockIdx.x] = sm[1023];
}

__global__ void scanB(int* bs, int nb) {
  if (threadIdx.x == 0) {
    int run = 0;
    for (int b = 0; b < nb; b++) { int t = bs[b]; bs[b] = run; run += t; }
  }
}

__global__ void scanC(const int* si, const int* cnt, const int* bs,
                      int* rp, int* wc, int n, int nE) {
  int i = blockIdx.x*1024 + threadIdx.x;
  if (i < n) { int ex = si[i] - cnt[i] + bs[blockIdx.x]; rp[i] = ex; wc[i] = ex; }
  if (i == n-1) rp[n] = nE;
}

__global__ void scat(const int* src, const int* dst, const float* ew,
                     int* wc, int2* pm, int nE) {
  int e = blockIdx.x*blockDim.x + threadIdx.x;
  if (e >= nE) return;
  int p = atomicAdd(&wc[dst[e]], 1);
  pm[p] = make_int2(src[e], __float_as_int(ew[e]));
}

// HGEMM via WMMA: C[M,128] fp16 = A[M,K] fp32 @ Bt[128,K] fp16 transposed.
// Block 128x128, BK=32, 8 warps as 4x2, warp tile 32x64, m16n16k16 fragments.
__global__ __launch_bounds__(256,2)
void hgemm(const float* A, const __half* Bt, __half* C, int M, int K) {
  __shared__ __half As[128*SA];
  __shared__ __half Bs[128*SA];
  __shared__ float stg[8][256];
  const int tid = threadIdx.x, lane = tid&31, wid = tid>>5;
  const int wm = wid&3, wn = wid>>2, row0 = blockIdx.x*128;

  wmma::fragment<wmma::accumulator,16,16,16,float> acc[2][4];
  for (int i = 0; i < 2; i++)
    for (int j = 0; j < 4; j++)
      wmma::fill_fragment(acc[i][j], 0.f);

  for (int k0 = 0; k0 < K; k0 += 32) {
    for (int it = 0; it < 4; it++) {
      int f = tid + it*256, r = f>>3, c4 = f&7;
      float4 v = make_float4(0.f, 0.f, 0.f, 0.f);
      if (row0+r < M) v = *(const float4*)(A + (size_t)(row0+r)*K + k0 + c4*4);
      __half2 h0 = __floats2half2_rn(v.x, v.y);
      __half2 h1 = __floats2half2_rn(v.z, v.w);
      uint2 pk;
      pk.x = *(unsigned*)&h0;
      pk.y = *(unsigned*)&h1;
      *(uint2*)(As + r*SA + c4*4) = pk;
      *(uint2*)(Bs + r*SA + c4*4) = *(const uint2*)(Bt + (size_t)r*K + k0 + c4*4);
    }
    __syncthreads();
    for (int kk = 0; kk < 2; kk++) {
      wmma::fragment<wmma::matrix_a,16,16,16,__half,wmma::row_major> fa[2];
      wmma::fragment<wmma::matrix_b,16,16,16,__half,wmma::col_major> fb[4];
      for (int mt = 0; mt < 2; mt++)
        wmma::load_matrix_sync(fa[mt], As + (wm*32 + mt*16)*SA + kk*16, SA);
      for (int nt = 0; nt < 4; nt++)
        wmma::load_matrix_sync(fb[nt], Bs + (wn*64 + nt*16)*SA + kk*16, SA);
      for (int mt = 0; mt < 2; mt++)
        for (int nt = 0; nt < 4; nt++)
          wmma::mma_sync(acc[mt][nt], fa[mt], fb[nt], acc[mt][nt]);
    }
    __syncthreads();
  }

  for (int mt = 0; mt < 2; mt++) {
    for (int nt = 0; nt < 4; nt++) {
      wmma::store_matrix_sync(stg[wid], acc[mt][nt], 16, wmma::mem_row_major);
      __syncwarp();
      int r0 = row0 + wm*32 + mt*16, c0 = wn*64 + nt*16;
      for (int i = lane; i < 128; i += 32) {
        int rr = i>>3, cc = (i&7)*2;
        if (r0+rr < M) {
          __half2 h = __floats2half2_rn(stg[wid][rr*16+cc], stg[wid][rr*16+cc+1]);
          *(__half2*)(C + (size_t)(r0+rr)*128 + c0 + cc) = h;
        }
      }
      __syncwarp();
    }
  }
}

__global__ __launch_bounds__(256)
void spmm(const __half* sup, const int* rp, const int2* pm,
          float* agg, float* cs, int n) {
  const int lane = threadIdx.x&31, wid = threadIdx.x>>5;
  const int gw = blockIdx.x*8 + wid, st = gridDim.x*8;
  float4 c4 = make_float4(0.f, 0.f, 0.f, 0.f);
  for (int nd = gw; nd < n; nd += st) {
    int beg = __ldg(rp+nd), end = __ldg(rp+nd+1);
    float4 a = make_float4(0.f, 0.f, 0.f, 0.f);
    for (int i = beg; i < end; i += 32) {
      int m = min(32, end-i);
      int2 ep = (lane < m) ? __ldg(pm+i+lane) : make_int2(0, 0);
#pragma unroll 4
      for (int j = 0; j < m; j++) {
        int s = __shfl_sync(0xffffffffu, ep.x, j);
        float w = __int_as_float(__shfl_sync(0xffffffffu, ep.y, j));
        uint2 rw = *(const uint2*)(sup + (size_t)s*128 + lane*4);
        float2 f0 = __half22float2(*(__half2*)&rw.x);
        float2 f1 = __half22float2(*(__half2*)&rw.y);
        a.x = fmaf(w, f0.x, a.x);
        a.y = fmaf(w, f0.y, a.y);
        a.z = fmaf(w, f1.x, a.z);
        a.w = fmaf(w, f1.y, a.w);
      }
    }
    *(float4*)(agg + (size_t)nd*128 + lane*4) = a;
    c4.x += a.x; c4.y += a.y; c4.z += a.z; c4.w += a.w;
  }
  __shared__ float sm[8][128];
  *(float4*)&sm[wid][lane*4] = c4;
  __syncthreads();
  if (threadIdx.x < 128) {
    float s = 0.f;
#pragma unroll
    for (int i = 0; i < 8; i++) s += sm[i][threadIdx.x];
    atomicAdd(&cs[threadIdx.x], s);
  }
}

__global__ __launch_bounds__(256)
void pnrelu(const float* agg, const float* cs, float* o, int n) {
  int row = (int)((blockIdx.x*(unsigned)blockDim.x + threadIdx.x) >> 5);
  if (row >= n) return;
  int lane = threadIdx.x&31;
  float iN = 1.0f/(float)n;
  float4 mu = *(const float4*)(cs + lane*4);
  float4 v = *(const float4*)(agg + (size_t)row*128 + lane*4);
  v.x -= mu.x*iN; v.y -= mu.y*iN; v.z -= mu.z*iN; v.w -= mu.w*iN;
  float ss = v.x*v.x + v.y*v.y + v.z*v.z + v.w*v.w;
#pragma unroll
  for (int q = 16; q; q >>= 1) ss += __shfl_xor_sync(0xffffffffu, ss, q);
  float iv = rsqrtf(1e-6f + ss);
  v.x = fmaxf(v.x*iv, 0.f);
  v.y = fmaxf(v.y*iv, 0.f);
  v.z = fmaxf(v.z*iv, 0.f);
  v.w = fmaxf(v.w*iv, 0.f);
  *(float4*)(o + (size_t)row*128 + lane*4) = v;
}

__global__ __launch_bounds__(256)
void fin(const float* agg, const float* cs, float* e2, float* pl, int n) {
  int row = (int)((blockIdx.x*(unsigned)blockDim.x + threadIdx.x) >> 5);
  if (row >= n) return;
  int lane = threadIdx.x&31;
  float iN = 1.0f/(float)n;
  float4 mu = *(const float4*)(cs + lane*4);
  float4 v = *(const float4*)(agg + (size_t)row*128 + lane*4);
  v.x -= mu.x*iN; v.y -= mu.y*iN; v.z -= mu.z*iN; v.w -= mu.w*iN;
  float ss = v.x*v.x + v.y*v.y + v.z*v.z + v.w*v.w;
#pragma unroll
  for (int q = 8; q; q >>= 1) ss += __shfl_xor_sync(0xffffffffu, ss, q);
  float iv = rsqrtf(1e-6f + ss);
  v.x *= iv; v.y *= iv; v.z *= iv; v.w *= iv;
  float mx = fmaxf(fmaxf(v.x, v.y), fmaxf(v.z, v.w));
#pragma unroll
  for (int q = 8; q; q >>= 1) mx = fmaxf(mx, __shfl_xor_sync(0xffffffffu, mx, q));
  float e0 = __expf(v.x-mx), e1 = __expf(v.y-mx);
  float ex2 = __expf(v.z-mx), e3 = __expf(v.w-mx);
  float es = e0 + e1 + ex2 + e3;
#pragma unroll
  for (int q = 8; q; q >>= 1) es += __shfl_xor_sync(0xffffffffu, es, q);
  float ei = 1.0f/es;
  if (lane < 16) {
    float4 r = make_float4(e0*ei, e1*ei, ex2*ei, e3*ei);
    *(float4*)(pl + (size_t)row*64 + lane*4) = r;
  } else {
    float4 r = make_float4(fmaxf(v.x, 0.f), fmaxf(v.y, 0.f),
                           fmaxf(v.z, 0.f), fmaxf(v.w, 0.f));
    *(float4*)(e2 + (size_t)row*64 + (lane-16)*4) = r;
  }
}

extern "C" void kernel_launch(void* const* d_in, const int* in_sizes, int n_in,
                              void* d_out, int out_size) {
  const float* x = (const float*)d_in[0];
  const int* es = (const int*)d_in[1];
  const int* ed = (const int*)d_in[2];
  const float* ew = (const float*)d_in[3];
  const float* w1 = (const float*)d_in[4];
  const float* wp = (const float*)d_in[6];
  const float* w2 = (const float*)d_in[8];
  const int nN = in_sizes[0] / 256;
  const int nE = in_sizes[1];
  float* b1;
  float* b2;
  float* cs;
  __half* hs;
  __half* wt;
  __half* wc2;
  int* ct;
  int* sc;
  int* bm;
  int* rp;
  int* wq;
  int2* pm;
  cudaGetSymbolAddress((void**)&b1, g_buf1);
  cudaGetSymbolAddress((void**)&b2, g_buf2);
  cudaGetSymbolAddress((void**)&hs, g_hsup);
  cudaGetSymbolAddress((void**)&wt, g_w1t);
  cudaGetSymbolAddress((void**)&wc2, g_wct);
  cudaGetSymbolAddress((void**)&cs, g_csum);
  cudaGetSymbolAddress((void**)&ct, g_cnt);
  cudaGetSymbolAddress((void**)&sc, g_scn);
  cudaGetSymbolAddress((void**)&bm, g_bsm);
  cudaGetSymbolAddress((void**)&rp, g_rp);
  cudaGetSymbolAddress((void**)&wq, g_wc);
  cudaGetSymbolAddress((void**)&pm, g_perm);
  float* outf = (float*)d_out;
  float* eo = outf;
  float* po = outf + (size_t)nN*64;
  int wg = (nN+7)/8;
  int eg = (nE+255)/256;
  int sg = 148*8;
  int nb = (nN+1023)/1024;
  int gg = (nN+127)/128;
  setup<<<(nN+255)/256,256>>>(ct, cs, nN);
  prep<<<128,256>>>(w1, wp, w2, wt, wc2);
  hist<<<eg,256>>>(ed, ct, nE);
  scanA<<<nb,1024>>>(ct, sc, bm, nN);
  scanB<<<1,32>>>(bm, nb);
  scanC<<<nb,1024>>>(sc, ct, bm, rp, wq, nN, nE);
  scat<<<eg,256>>>(es, ed, ew, wq, pm, nE);
  hgemm<<<gg,256>>>(x, wt, hs, nN, 256);
  spmm<<<sg,256>>>(hs, rp, pm, b2, cs, nN);
  pnrelu<<<wg,256>>>(b2, cs, b1, nN);
  hgemm<<<gg,256>>>(b1, wc2, hs, nN, 128);
  spmm<<<sg,256>>>(hs, rp, pm, b2, cs+128, nN);
  fin<<<wg,256>>>(b2, cs+128, eo, po, nN);
}

// round 13
// speedup vs baseline: 3.0320x; 1.0824x over previous
#include <cuda_runtime.h>
#include <cuda_fp16.h>
#include <mma.h>
using namespace nvcuda;

#define NMAX 100000
#define SA 40

__device__ float  g_buf2[(size_t)NMAX*128];
__device__ __half g_hsup[(size_t)NMAX*128];
__device__ __half g_enc1[(size_t)NMAX*128];
__device__ __half g_w1t[128*256];
__device__ __half g_wct[128*128];
__device__ float  g_csum[256];
__device__ int    g_cnt[NMAX];
__device__ int    g_scn[NMAX];
__device__ int    g_bsm[98];
__device__ int    g_rp[NMAX+1];
__device__ int    g_wc[NMAX];
__device__ int2   g_perm[1600000];

__global__ void setup(int* cnt, float* cs, int n) {
  int i = blockIdx.x*blockDim.x + threadIdx.x;
  if (i < n) cnt[i] = 0;
  if (i < 256) cs[i] = 0.f;
}

__global__ void prep(const float* w1, const float* wp, const float* w2,
                     __half* w1t, __half* wct) {
  int i = blockIdx.x*blockDim.x + threadIdx.x;
  if (i < 256*128) { int k = i>>7, n = i&127; w1t[n*256+k] = __float2half(w1[i]); }
  if (i < 128*64) {
    int k = i>>6, c = i&63;
    wct[c*128+k] = __float2half(wp[i]);
    wct[(64+c)*128+k] = __float2half(w2[i]);
  }
}

__global__ void hist(const int* dst, int* cnt, int nE) {
  int e = blockIdx.x*blockDim.x + threadIdx.x;
  if (e < nE) atomicAdd(&cnt[dst[e]], 1);
}

__global__ void scanA(const int* cnt, int* so, int* bs, int n) {
  __shared__ int sm[1024];
  int i = blockIdx.x*1024 + threadIdx.x;
  sm[threadIdx.x] = (i < n) ? cnt[i] : 0;
  __syncthreads();
  for (int o = 1; o < 1024; o <<= 1) {
    int t = (threadIdx.x >= o) ? sm[threadIdx.x-o] : 0;
    __syncthreads();
    sm[threadIdx.x] += t;
    __syncthreads();
  }
  if (i < n) so[i] = sm[threadIdx.x];
  if (threadIdx.x == 1023) bs[blockIdx.x] = sm[1023];
}

__global__ void scanB(int* bs, int nb) {
  if (threadIdx.x == 0) {
    int run = 0;
    for (int b = 0; b < nb; b++) { int t = bs[b]; bs[b] = run; run += t; }
  }
}

__global__ void scanC(const int* si, const int* cnt, const int* bs,
                      int* rp, int* wc, int n, int nE) {
  int i = blockIdx.x*1024 + threadIdx.x;
  if (i < n) { int ex = si[i] - cnt[i] + bs[blockIdx.x]; rp[i] = ex; wc[i] = ex; }
  if (i == n-1) rp[n] = nE;
}

__global__ void scat(const int* src, const int* dst, const float* ew,
                     int* wc, int2* pm, int nE) {
  int e = blockIdx.x*blockDim.x + threadIdx.x;
  if (e >= nE) return;
  int p = atomicAdd(&wc[dst[e]], 1);
  pm[p] = make_int2(src[e], __float_as_int(ew[e]));
}

__device__ __forceinline__ uint2 ldA4(const float* p, bool ok) {
  float4 v = ok ? *(const float4*)p : make_float4(0.f, 0.f, 0.f, 0.f);
  __half2 h0 = __floats2half2_rn(v.x, v.y);
  __half2 h1 = __floats2half2_rn(v.z, v.w);
  uint2 pk;
  pk.x = *(unsigned*)&h0;
  pk.y = *(unsigned*)&h1;
  return pk;
}
__device__ __forceinline__ uint2 ldA4(const __half* p, bool ok) {
  if (ok) return *(const uint2*)p;
  return make_uint2(0u, 0u);
}

// HGEMM via WMMA: C[M,128] fp16 = A[M,K] @ Bt[128,K]^T.
// Block 128x128, BK=32, 8 warps as 4x2, warp tile 32x64, m16n16k16.
template<typename TA>
__global__ __launch_bounds__(256,2)
void hgemm(const TA* A, const __half* Bt, __half* C, int M, int K) {
  __shared__ __half As[128*SA];
  __shared__ __half Bs[128*SA];
  __shared__ float stg[8][256];
  const int tid = threadIdx.x, lane = tid&31, wid = tid>>5;
  const int wm = wid&3, wn = wid>>2, row0 = blockIdx.x*128;

  wmma::fragment<wmma::accumulator,16,16,16,float> acc[2][4];
  for (int i = 0; i < 2; i++)
    for (int j = 0; j < 4; j++)
      wmma::fill_fragment(acc[i][j], 0.f);

  for (int k0 = 0; k0 < K; k0 += 32) {
    for (int it = 0; it < 4; it++) {
      int f = tid + it*256, r = f>>3, c4 = f&7;
      uint2 pk = ldA4(A + (size_t)(row0+r)*K + k0 + c4*4, row0+r < M);
      *(uint2*)(As + r*SA + c4*4) = pk;
      *(uint2*)(Bs + r*SA + c4*4) = *(const uint2*)(Bt + (size_t)r*K + k0 + c4*4);
    }
    __syncthreads();
    for (int kk = 0; kk < 2; kk++) {
      wmma::fragment<wmma::matrix_a,16,16,16,__half,wmma::row_major> fa[2];
      wmma::fragment<wmma::matrix_b,16,16,16,__half,wmma::col_major> fb[4];
      for (int mt = 0; mt < 2; mt++)
        wmma::load_matrix_sync(fa[mt], As + (wm*32 + mt*16)*SA + kk*16, SA);
      for (int nt = 0; nt < 4; nt++)
        wmma::load_matrix_sync(fb[nt], Bs + (wn*64 + nt*16)*SA + kk*16, SA);
      for (int mt = 0; mt < 2; mt++)
        for (int nt = 0; nt < 4; nt++)
          wmma::mma_sync(acc[mt][nt], fa[mt], fb[nt], acc[mt][nt]);
    }
    __syncthreads();
  }

  for (int mt = 0; mt < 2; mt++) {
    for (int nt = 0; nt < 4; nt++) {
      wmma::store_matrix_sync(stg[wid], acc[mt][nt], 16, wmma::mem_row_major);
      __syncwarp();
      int r0 = row0 + wm*32 + mt*16, c0 = wn*64 + nt*16;
      for (int i = lane; i < 128; i += 32) {
        int rr = i>>3, cc = (i&7)*2;
        if (r0+rr < M) {
          __half2 h = __floats2half2_rn(stg[wid][rr*16+cc], stg[wid][rr*16+cc+1]);
          *(__half2*)(C + (size_t)(r0+rr)*128 + c0 + cc) = h;
        }
      }
      __syncwarp();
    }
  }
}

__global__ __launch_bounds__(256)
void spmm(const __half* sup, const int* rp, const int2* pm,
          float* agg, float* cs, int n) {
  const int lane = threadIdx.x&31, wid = threadIdx.x>>5;
  const int gw = blockIdx.x*8 + wid, st = gridDim.x*8;
  float4 c4 = make_float4(0.f, 0.f, 0.f, 0.f);
  for (int nd = gw; nd < n; nd += st) {
    int beg = __ldg(rp+nd), end = __ldg(rp+nd+1);
    float4 a = make_float4(0.f, 0.f, 0.f, 0.f);
    for (int i = beg; i < end; i += 32) {
      int m = min(32, end-i);
      int2 ep = (lane < m) ? __ldg(pm+i+lane) : make_int2(0, 0);
#pragma unroll 4
      for (int j = 0; j < m; j++) {
        int s = __shfl_sync(0xffffffffu, ep.x, j);
        float w = __int_as_float(__shfl_sync(0xffffffffu, ep.y, j));
        uint2 rw = *(const uint2*)(sup + (size_t)s*128 + lane*4);
        float2 f0 = __half22float2(*(__half2*)&rw.x);
        float2 f1 = __half22float2(*(__half2*)&rw.y);
        a.x = fmaf(w, f0.x, a.x);
        a.y = fmaf(w, f0.y, a.y);
        a.z = fmaf(w, f1.x, a.z);
        a.w = fmaf(w, f1.y, a.w);
      }
    }
    *(float4*)(agg + (size_t)nd*128 + lane*4) = a;
    c4.x += a.x; c4.y += a.y; c4.z += a.z; c4.w += a.w;
  }
  __shared__ float sm[8][128];
  *(float4*)&sm[wid][lane*4] = c4;
  __syncthreads();
  if (threadIdx.x < 128) {
    float s = 0.f;
#pragma unroll
    for (int i = 0; i < 8; i++) s += sm[i][threadIdx.x];
    atomicAdd(&cs[threadIdx.x], s);
  }
}

__global__ __launch_bounds__(256)
void pnrelu(const float* agg, const float* cs, __half* o, int n) {
  int row = (int)((blockIdx.x*(unsigned)blockDim.x + threadIdx.x) >> 5);
  if (row >= n) return;
  int lane = threadIdx.x&31;
  float iN = 1.0f/(float)n;
  float4 mu = *(const float4*)(cs + lane*4);
  float4 v = *(const float4*)(agg + (size_t)row*128 + lane*4);
  v.x -= mu.x*iN; v.y -= mu.y*iN; v.z -= mu.z*iN; v.w -= mu.w*iN;
  float ss = v.x*v.x + v.y*v.y + v.z*v.z + v.w*v.w;
#pragma unroll
  for (int q = 16; q; q >>= 1) ss += __shfl_xor_sync(0xffffffffu, ss, q);
  float iv = rsqrtf(1e-6f + ss);
  __half2 h0 = __floats2half2_rn(fmaxf(v.x*iv, 0.f), fmaxf(v.y*iv, 0.f));
  __half2 h1 = __floats2half2_rn(fmaxf(v.z*iv, 0.f), fmaxf(v.w*iv, 0.f));
  uint2 pk;
  pk.x = *(unsigned*)&h0;
  pk.y = *(unsigned*)&h1;
  *(uint2*)(o + (size_t)row*128 + lane*4) = pk;
}

__global__ __launch_bounds__(256)
void fin(const float* agg, const float* cs, float* e2, float* pl, int n) {
  int row = (int)((blockIdx.x*(unsigned)blockDim.x + threadIdx.x) >> 5);
  if (row >= n) return;
  int lane = threadIdx.x&31;
  float iN = 1.0f/(float)n;
  float4 mu = *(const float4*)(cs + lane*4);
  float4 v = *(const float4*)(agg + (size_t)row*128 + lane*4);
  v.x -= mu.x*iN; v.y -= mu.y*iN; v.z -= mu.z*iN; v.w -= mu.w*iN;
  float ss = v.x*v.x + v.y*v.y + v.z*v.z + v.w*v.w;
#pragma unroll
  for (int q = 8; q; q >>= 1) ss += __shfl_xor_sync(0xffffffffu, ss, q);
  float iv = rsqrtf(1e-6f + ss);
  v.x *= iv; v.y *= iv; v.z *= iv; v.w *= iv;
  float mx = fmaxf(fmaxf(v.x, v.y), fmaxf(v.z, v.w));
#pragma unroll
  for (int q = 8; q; q >>= 1) mx = fmaxf(mx, __shfl_xor_sync(0xffffffffu, mx, q));
  float e0 = __expf(v.x-mx), e1 = __expf(v.y-mx);
  float ex2 = __expf(v.z-mx), e3 = __expf(v.w-mx);
  float es = e0 + e1 + ex2 + e3;
#pragma unroll
  for (int q = 8; q; q >>= 1) es += __shfl_xor_sync(0xffffffffu, es, q);
  float ei = 1.0f/es;
  if (lane < 16) {
    float4 r = make_float4(e0*ei, e1*ei, ex2*ei, e3*ei);
    *(float4*)(pl + (size_t)row*64 + lane*4) = r;
  } else {
    float4 r = make_float4(fmaxf(v.x, 0.f), fmaxf(v.y, 0.f),
                           fmaxf(v.z, 0.f), fmaxf(v.w, 0.f));
    *(float4*)(e2 + (size_t)row*64 + (lane-16)*4) = r;
  }
}

extern "C" void kernel_launch(void* const* d_in, const int* in_sizes, int n_in,
                              void* d_out, int out_size) {
  const float* x = (const float*)d_in[0];
  const int* es = (const int*)d_in[1];
  const int* ed = (const int*)d_in[2];
  const float* ew = (const float*)d_in[3];
  const float* w1 = (const float*)d_in[4];
  const float* wp = (const float*)d_in[6];
  const float* w2 = (const float*)d_in[8];
  const int nN = in_sizes[0] / 256;
  const int nE = in_sizes[1];
  float* b2;
  float* cs;
  __half* hs;
  __half* e1h;
  __half* wt;
  __half* wc2;
  int* ct;
  int* sc;
  int* bm;
  int* rp;
  int* wq;
  int2* pm;
  cudaGetSymbolAddress((void**)&b2, g_buf2);
  cudaGetSymbolAddress((void**)&hs, g_hsup);
  cudaGetSymbolAddress((void**)&e1h, g_enc1);
  cudaGetSymbolAddress((void**)&wt, g_w1t);
  cudaGetSymbolAddress((void**)&wc2, g_wct);
  cudaGetSymbolAddress((void**)&cs, g_csum);
  cudaGetSymbolAddress((void**)&ct, g_cnt);
  cudaGetSymbolAddress((void**)&sc, g_scn);
  cudaGetSymbolAddress((void**)&bm, g_bsm);
  cudaGetSymbolAddress((void**)&rp, g_rp);
  cudaGetSymbolAddress((void**)&wq, g_wc);
  cudaGetSymbolAddress((void**)&pm, g_perm);
  float* outf = (float*)d_out;
  float* eo = outf;
  float* po = outf + (size_t)nN*64;
  int wg = (nN+7)/8;
  int eg = (nE+255)/256;
  int sg = 148*8;
  int nb = (nN+1023)/1024;
  int gg = (nN+127)/128;

  cudaStream_t s2;
  cudaStreamCreateWithFlags(&s2, cudaStreamNonBlocking);
  cudaEvent_t ev0, ev1;
  cudaEventCreateWithFlags(&ev0, cudaEventDisableTiming);
  cudaEventCreateWithFlags(&ev1, cudaEventDisableTiming);

  // fork: CSR build on side stream, weight prep + GEMM1 on main stream
  cudaEventRecord(ev0, 0);
  cudaStreamWaitEvent(s2, ev0, 0);
  setup<<<(nN+255)/256, 256, 0, s2>>>(ct, cs, nN);
  hist<<<eg, 256, 0, s2>>>(ed, ct, nE);
  scanA<<<nb, 1024, 0, s2>>>(ct, sc, bm, nN);
  scanB<<<1, 32, 0, s2>>>(bm, nb);
  scanC<<<nb, 1024, 0, s2>>>(sc, ct, bm, rp, wq, nN, nE);
  scat<<<eg, 256, 0, s2>>>(es, ed, ew, wq, pm, nE);
  cudaEventRecord(ev1, s2);

  prep<<<128, 256>>>(w1, wp, w2, wt, wc2);
  hgemm<float><<<gg, 256>>>(x, wt, hs, nN, 256);

  // join
  cudaStreamWaitEvent(0, ev1, 0);
  spmm<<<sg, 256>>>(hs, rp, pm, b2, cs, nN);
  pnrelu<<<wg, 256>>>(b2, cs, e1h, nN);
  hgemm<__half><<<gg, 256>>>(e1h, wc2, hs, nN, 128);
  spmm<<<sg, 256>>>(hs, rp, pm, b2, cs+128, nN);
  fin<<<wg, 256>>>(b2, cs+128, eo, po, nN);
}